// round 9
// baseline (speedup 1.0000x reference)
#include <cuda_runtime.h>

// BYOL loss: out = 2 - 2 * mean_i( dot(x_i, xt_i) / (max(||x_i||,eps)*max(||xt_i||,eps)) )
// 512 blocks x 256 threads; each warp handles 2 rows, all 16 LDG.128 issued
// up-front for max MLP; streaming loads; last-block-retires reduce.

#define N_ROWS 8192
#define D_DIM  512
#define EPS 1e-8f

#define NTHREADS 256
#define WARPS_PER_BLOCK 8
#define ROWS_PER_WARP 2
#define NBLOCKS (N_ROWS / (WARPS_PER_BLOCK * ROWS_PER_WARP))  // 512

__device__ float g_partial[NBLOCKS];
__device__ unsigned int g_count = 0;

__global__ void __launch_bounds__(NTHREADS) byol_fused_kernel(
    const float* __restrict__ x, const float* __restrict__ xt,
    float* __restrict__ out)
{
    const int t = threadIdx.x;
    const int lane = t & 31;
    const int warp = t >> 5;
    const int gwarp = blockIdx.x * WARPS_PER_BLOCK + warp;
    const int row0 = gwarp * ROWS_PER_WARP;

    const float4* a4 = reinterpret_cast<const float4*>(x  + (size_t)row0 * D_DIM);
    const float4* b4 = reinterpret_cast<const float4*>(xt + (size_t)row0 * D_DIM);
    const int ROW4 = D_DIM / 4;  // 128 float4 per row

    // Issue ALL 16 loads up front (2 rows x (4 A + 4 B)) for max MLP.
    float4 A0[4], B0[4], A1[4], B1[4];
    #pragma unroll
    for (int i = 0; i < 4; i++) A0[i] = __ldcs(&a4[lane + 32 * i]);
    #pragma unroll
    for (int i = 0; i < 4; i++) B0[i] = __ldcs(&b4[lane + 32 * i]);
    #pragma unroll
    for (int i = 0; i < 4; i++) A1[i] = __ldcs(&a4[ROW4 + lane + 32 * i]);
    #pragma unroll
    for (int i = 0; i < 4; i++) B1[i] = __ldcs(&b4[ROW4 + lane + 32 * i]);

    // ---- row 0 ----
    float d0 = 0.f, aa0 = 0.f, bb0 = 0.f;
    #pragma unroll
    for (int i = 0; i < 4; i++) {
        float4 av = A0[i], bv = B0[i];
        d0  += av.x*bv.x + av.y*bv.y + av.z*bv.z + av.w*bv.w;
        aa0 += av.x*av.x + av.y*av.y + av.z*av.z + av.w*av.w;
        bb0 += bv.x*bv.x + bv.y*bv.y + bv.z*bv.z + bv.w*bv.w;
    }
    // ---- row 1 ----
    float d1 = 0.f, aa1 = 0.f, bb1 = 0.f;
    #pragma unroll
    for (int i = 0; i < 4; i++) {
        float4 av = A1[i], bv = B1[i];
        d1  += av.x*bv.x + av.y*bv.y + av.z*bv.z + av.w*bv.w;
        aa1 += av.x*av.x + av.y*av.y + av.z*av.z + av.w*av.w;
        bb1 += bv.x*bv.x + bv.y*bv.y + bv.z*bv.z + bv.w*bv.w;
    }

    // 6 independent shuffle chains overlap well.
    #pragma unroll
    for (int off = 16; off > 0; off >>= 1) {
        d0  += __shfl_xor_sync(0xFFFFFFFFu, d0,  off);
        aa0 += __shfl_xor_sync(0xFFFFFFFFu, aa0, off);
        bb0 += __shfl_xor_sync(0xFFFFFFFFu, bb0, off);
        d1  += __shfl_xor_sync(0xFFFFFFFFu, d1,  off);
        aa1 += __shfl_xor_sync(0xFFFFFFFFu, aa1, off);
        bb1 += __shfl_xor_sync(0xFFFFFFFFu, bb1, off);
    }

    __shared__ float s_cos[WARPS_PER_BLOCK];
    if (lane == 0) {
        float c0 = d0 / (fmaxf(sqrtf(aa0), EPS) * fmaxf(sqrtf(bb0), EPS));
        float c1 = d1 / (fmaxf(sqrtf(aa1), EPS) * fmaxf(sqrtf(bb1), EPS));
        s_cos[warp] = c0 + c1;
    }
    __syncthreads();

    __shared__ bool s_last;
    if (t == 0) {
        float p = 0.f;
        #pragma unroll
        for (int i = 0; i < WARPS_PER_BLOCK; i++) p += s_cos[i];
        g_partial[blockIdx.x] = p;
        __threadfence();
        // wraps to 0 when old == NBLOCKS-1 -> self-resets for graph replay
        unsigned int old = atomicInc(&g_count, NBLOCKS - 1);
        s_last = (old == NBLOCKS - 1);
    }
    __syncthreads();

    if (!s_last) return;

    // ---- last block: deterministic reduce of 512 partials ----
    float s = 0.f;
    #pragma unroll
    for (int i = 0; i < NBLOCKS / NTHREADS; i++)
        s += g_partial[t + NTHREADS * i];

    #pragma unroll
    for (int off = 16; off > 0; off >>= 1)
        s += __shfl_xor_sync(0xFFFFFFFFu, s, off);

    __shared__ float s_w[WARPS_PER_BLOCK];
    if (lane == 0) s_w[warp] = s;
    __syncthreads();

    if (t == 0) {
        float v = 0.f;
        #pragma unroll
        for (int i = 0; i < WARPS_PER_BLOCK; i++) v += s_w[i];
        out[0] = 2.0f - 2.0f * (v / (float)N_ROWS);
    }
}

extern "C" void kernel_launch(void* const* d_in, const int* in_sizes, int n_in,
                              void* d_out, int out_size)
{
    const float* x  = (const float*)d_in[0];
    const float* xt = (const float*)d_in[1];
    float* out = (float*)d_out;

    byol_fused_kernel<<<NBLOCKS, NTHREADS>>>(x, xt, out);
}